// round 10
// baseline (speedup 1.0000x reference)
#include <cuda_runtime.h>
#include <cstddef>

// SNN: 2-2-2 spiking net, B=500k independent elements, T=32 steps.
// History:
//   R3: 1 elem/thread, float2 stcs        57.8us  DRAM 70.9%
//   R4: pairs/float4, 977 CTAs            67.6us
//   R5: grid-stride 888                   63.6us
//   R8: 4x8-step chunks                   62.0us  (issue-bound, 66%)
//   R9: 2x16-step chunks, LPT             60.1us  DRAM 70.0%
// All well-scheduled variants pin at ~70% DRAM (ncu) / ~6.6TB/s wall-clock:
// the HBM pure-write ceiling. R10: cut steady-state DRAM traffic instead.
// spk1 (128MB ~ L2 capacity) is stored with NORMAL eviction priority while
// spk2/mem2 use evict-first (__stcs). Streaming lines recycle their own L2
// ways, so spk1 lines stay resident across graph replays and are overwritten
// in place (write hits, no DRAM drain) -> DRAM/replay ~384MB -> ~270MB.
//
// FP association mirrors XLA exactly (verified rel_err==0):
//   dot:  acc = fma(x1, w[j][1], rnd(x0*w[j][0]));  bias: cur = acc + b[j]
//   mem:  ((beta*mem + cur) - reset) with separate rn ops
//   reset at step t == spike at step t-1 (carried, exact: s in {0,1})
//
// Output layout: [spk1 | spk2 | mem2], each [T,B,2] float32.

#define SNN_STEP()                                                              \
    do {                                                                        \
        const float r1_0 = s1_0 != 0.f ? th1 : 0.f;                             \
        const float r1_1 = s1_1 != 0.f ? th1 : 0.f;                             \
        mem1_0 = __fsub_rn(__fadd_rn(__fmul_rn(bt1, mem1_0), cur1_0), r1_0);    \
        mem1_1 = __fsub_rn(__fadd_rn(__fmul_rn(bt1, mem1_1), cur1_1), r1_1);    \
        s1_0 = (mem1_0 > th1) ? 1.f : 0.f;                                      \
        s1_1 = (mem1_1 > th1) ? 1.f : 0.f;                                      \
        const float cur2_0 =                                                    \
            __fadd_rn(__fmaf_rn(s1_1, w2_01, __fmul_rn(s1_0, w2_00)), b2_0);    \
        const float cur2_1 =                                                    \
            __fadd_rn(__fmaf_rn(s1_1, w2_11, __fmul_rn(s1_0, w2_10)), b2_1);    \
        const float r2_0 = s2_0 != 0.f ? th2 : 0.f;                             \
        const float r2_1 = s2_1 != 0.f ? th2 : 0.f;                             \
        mem2_0 = __fsub_rn(__fadd_rn(__fmul_rn(bt2, mem2_0), cur2_0), r2_0);    \
        mem2_1 = __fsub_rn(__fadd_rn(__fmul_rn(bt2, mem2_1), cur2_1), r2_1);    \
        s2_0 = (mem2_0 > th2) ? 1.f : 0.f;                                      \
        s2_1 = (mem2_1 > th2) ? 1.f : 0.f;                                      \
    } while (0)

#define SNN_LOAD_PARAMS()                                                       \
    const float w1_00 = __ldg(fc1_w + 0), w1_01 = __ldg(fc1_w + 1);             \
    const float w1_10 = __ldg(fc1_w + 2), w1_11 = __ldg(fc1_w + 3);             \
    const float b1_0  = __ldg(fc1_b + 0), b1_1  = __ldg(fc1_b + 1);             \
    const float w2_00 = __ldg(fc2_w + 0), w2_01 = __ldg(fc2_w + 1);             \
    const float w2_10 = __ldg(fc2_w + 2), w2_11 = __ldg(fc2_w + 3);             \
    const float b2_0  = __ldg(fc2_b + 0), b2_1  = __ldg(fc2_b + 1);             \
    const float bt1   = fminf(fmaxf(__ldg(beta1), 0.f), 1.f);                   \
    const float bt2   = fminf(fmaxf(__ldg(beta2), 0.f), 1.f);                   \
    const float th1   = __ldg(thr1);                                            \
    const float th2   = __ldg(thr2)

template<int T_STEPS>
__global__ __launch_bounds__(256)
void snn_resident(const float2* __restrict__ x,
                  const float* __restrict__ fc1_w, const float* __restrict__ fc1_b,
                  const float* __restrict__ beta1, const float* __restrict__ thr1,
                  const float* __restrict__ fc2_w, const float* __restrict__ fc2_b,
                  const float* __restrict__ beta2, const float* __restrict__ thr2,
                  float2* __restrict__ out, int B, int T_dyn)
{
    const int b = blockIdx.x * blockDim.x + threadIdx.x;
    if (b >= B) return;

    SNN_LOAD_PARAMS();

    const float2 xv = __ldg(&x[b]);
    const float cur1_0 = __fadd_rn(__fmaf_rn(xv.y, w1_01, __fmul_rn(xv.x, w1_00)), b1_0);
    const float cur1_1 = __fadd_rn(__fmaf_rn(xv.y, w1_11, __fmul_rn(xv.x, w1_10)), b1_1);

    float mem1_0 = 0.f, mem1_1 = 0.f, mem2_0 = 0.f, mem2_1 = 0.f;
    // initial "previous spike" = Heaviside(0 - th) (reference's reset at t=0)
    float s1_0 = (0.f > th1) ? 1.f : 0.f;
    float s1_1 = s1_0;
    float s2_0 = (0.f > th2) ? 1.f : 0.f;
    float s2_1 = s2_0;

    const int T = (T_STEPS > 0) ? T_STEPS : T_dyn;
    const size_t TB = (size_t)T * (size_t)B;
    float2* __restrict__ o_spk1 = out;
    float2* __restrict__ o_spk2 = out + TB;
    float2* __restrict__ o_mem2 = out + 2 * TB;

#pragma unroll
    for (int t = 0; t < T; t++) {
        SNN_STEP();
        const size_t idx = (size_t)t * (size_t)B + (size_t)b;
        // spk1: NORMAL eviction priority -> stays resident in L2 across
        // replays (overwritten in place, no DRAM drain in steady state).
        o_spk1[idx] = make_float2(s1_0, s1_1);
        // spk2/mem2: evict-first streaming -> recycle their own L2 ways.
        __stcs(&o_spk2[idx], make_float2(s2_0, s2_1));
        __stcs(&o_mem2[idx], make_float2(mem2_0, mem2_1));
    }
}

extern "C" void kernel_launch(void* const* d_in, const int* in_sizes, int n_in,
                              void* d_out, int out_size) {
    const float2* x     = (const float2*)d_in[0];
    const float*  fc1_w = (const float*)d_in[1];
    const float*  fc1_b = (const float*)d_in[2];
    const float*  beta1 = (const float*)d_in[3];
    const float*  thr1  = (const float*)d_in[4];
    const float*  fc2_w = (const float*)d_in[5];
    const float*  fc2_b = (const float*)d_in[6];
    const float*  beta2 = (const float*)d_in[7];
    const float*  thr2  = (const float*)d_in[8];

    const int B = in_sizes[0] / 2;          // x is [B, 2]
    const int T = out_size / (6 * B);       // out = 3 arrays of [T, B, 2]

    const int threads = 256;
    const int blocks = (B + threads - 1) / threads;

    if (T == 32) {
        snn_resident<32><<<blocks, threads>>>(x, fc1_w, fc1_b, beta1, thr1,
                                              fc2_w, fc2_b, beta2, thr2,
                                              (float2*)d_out, B, T);
    } else {
        snn_resident<0><<<blocks, threads>>>(x, fc1_w, fc1_b, beta1, thr1,
                                             fc2_w, fc2_b, beta2, thr2,
                                             (float2*)d_out, B, T);
    }
}

// round 13
// speedup vs baseline: 1.0062x; 1.0062x over previous
#include <cuda_runtime.h>
#include <cstddef>

// SNN: 2-2-2 spiking net, B=500k independent elements, T=32 steps.
// History:
//   R3:  1 elem/thread, float2 stcs, 1954 CTAs   57.8us  (best)  DRAM 70.9%
//   R4:  pairs/float4, 977 CTAs                  67.6us  (1.1-wave tail)
//   R5:  grid-stride 888                         63.6us
//   R8:  4x8-step chunks                         62.0us  (issue 66%)
//   R9:  2x16-step chunks                        60.1us
//   R10: L2-residency hint                       62.0us  (hint ineffective)
// Steady-state write BW is ~6.64TB/s (83% of spec). R11 tests the last
// untried axis: STG.128 burst width WITH R3's wave structure.
//   item = (pair p, 16-step chunk c); items = 2*(B/2) = B -> 1954 CTAs,
//   identical 2.2-wave balance to R3, LPT heavy-chunk-first, float4 stores.
//
// FP association mirrors XLA exactly (verified rel_err==0):
//   dot:  acc = fma(x1, w[j][1], rnd(x0*w[j][0]));  bias: cur = acc + b[j]
//   mem:  ((beta*mem + cur) - reset) with separate rn ops
//   reset at step t == spike at step t-1 (carried, exact: s in {0,1})
//
// Output layout: [spk1 | spk2 | mem2], each [T,B,2] float32.

// One recurrence step for BOTH elements of a pair (A and B).
#define SNN_STEP2()                                                             \
    do {                                                                        \
        const float r1A0 = s1A0 != 0.f ? th1 : 0.f;                             \
        const float r1A1 = s1A1 != 0.f ? th1 : 0.f;                             \
        const float r1B0 = s1B0 != 0.f ? th1 : 0.f;                             \
        const float r1B1 = s1B1 != 0.f ? th1 : 0.f;                             \
        m1A0 = __fsub_rn(__fadd_rn(__fmul_rn(bt1, m1A0), c1A0), r1A0);          \
        m1A1 = __fsub_rn(__fadd_rn(__fmul_rn(bt1, m1A1), c1A1), r1A1);          \
        m1B0 = __fsub_rn(__fadd_rn(__fmul_rn(bt1, m1B0), c1B0), r1B0);          \
        m1B1 = __fsub_rn(__fadd_rn(__fmul_rn(bt1, m1B1), c1B1), r1B1);          \
        s1A0 = (m1A0 > th1) ? 1.f : 0.f;                                        \
        s1A1 = (m1A1 > th1) ? 1.f : 0.f;                                        \
        s1B0 = (m1B0 > th1) ? 1.f : 0.f;                                        \
        s1B1 = (m1B1 > th1) ? 1.f : 0.f;                                        \
        const float c2A0 =                                                      \
            __fadd_rn(__fmaf_rn(s1A1, w2_01, __fmul_rn(s1A0, w2_00)), b2_0);    \
        const float c2A1 =                                                      \
            __fadd_rn(__fmaf_rn(s1A1, w2_11, __fmul_rn(s1A0, w2_10)), b2_1);    \
        const float c2B0 =                                                      \
            __fadd_rn(__fmaf_rn(s1B1, w2_01, __fmul_rn(s1B0, w2_00)), b2_0);    \
        const float c2B1 =                                                      \
            __fadd_rn(__fmaf_rn(s1B1, w2_11, __fmul_rn(s1B0, w2_10)), b2_1);    \
        const float r2A0 = s2A0 != 0.f ? th2 : 0.f;                             \
        const float r2A1 = s2A1 != 0.f ? th2 : 0.f;                             \
        const float r2B0 = s2B0 != 0.f ? th2 : 0.f;                             \
        const float r2B1 = s2B1 != 0.f ? th2 : 0.f;                             \
        m2A0 = __fsub_rn(__fadd_rn(__fmul_rn(bt2, m2A0), c2A0), r2A0);          \
        m2A1 = __fsub_rn(__fadd_rn(__fmul_rn(bt2, m2A1), c2A1), r2A1);          \
        m2B0 = __fsub_rn(__fadd_rn(__fmul_rn(bt2, m2B0), c2B0), r2B0);          \
        m2B1 = __fsub_rn(__fadd_rn(__fmul_rn(bt2, m2B1), c2B1), r2B1);          \
        s2A0 = (m2A0 > th2) ? 1.f : 0.f;                                        \
        s2A1 = (m2A1 > th2) ? 1.f : 0.f;                                        \
        s2B0 = (m2B0 > th2) ? 1.f : 0.f;                                        \
        s2B1 = (m2B1 > th2) ? 1.f : 0.f;                                        \
    } while (0)

#define SNN_LOAD_PARAMS()                                                       \
    const float w1_00 = __ldg(fc1_w + 0), w1_01 = __ldg(fc1_w + 1);             \
    const float w1_10 = __ldg(fc1_w + 2), w1_11 = __ldg(fc1_w + 3);             \
    const float b1_0  = __ldg(fc1_b + 0), b1_1  = __ldg(fc1_b + 1);             \
    const float w2_00 = __ldg(fc2_w + 0), w2_01 = __ldg(fc2_w + 1);             \
    const float w2_10 = __ldg(fc2_w + 2), w2_11 = __ldg(fc2_w + 3);             \
    const float b2_0  = __ldg(fc2_b + 0), b2_1  = __ldg(fc2_b + 1);             \
    const float bt1   = fminf(fmaxf(__ldg(beta1), 0.f), 1.f);                   \
    const float bt2   = fminf(fmaxf(__ldg(beta2), 0.f), 1.f);                   \
    const float th1   = __ldg(thr1);                                            \
    const float th2   = __ldg(thr2)

// T=32, even B: item = (pair, 16-step half), heavy half first (LPT).
__global__ __launch_bounds__(256)
void snn_pair_half32(const float4* __restrict__ x,
                     const float* __restrict__ fc1_w, const float* __restrict__ fc1_b,
                     const float* __restrict__ beta1, const float* __restrict__ thr1,
                     const float* __restrict__ fc2_w, const float* __restrict__ fc2_b,
                     const float* __restrict__ beta2, const float* __restrict__ thr2,
                     float4* __restrict__ out, int Bp)
{
    const int gid = blockIdx.x * blockDim.x + threadIdx.x;
    if (gid >= 2 * Bp) return;

    const bool heavy = (gid < Bp);       // LPT: chunk 1 (more work) first
    const int p = heavy ? gid : gid - Bp;
    const int c = heavy ? 1 : 0;

    SNN_LOAD_PARAMS();

    const float4 xv = __ldg(&x[p]);      // elem A = (x,y), elem B = (z,w)
    const float c1A0 = __fadd_rn(__fmaf_rn(xv.y, w1_01, __fmul_rn(xv.x, w1_00)), b1_0);
    const float c1A1 = __fadd_rn(__fmaf_rn(xv.y, w1_11, __fmul_rn(xv.x, w1_10)), b1_1);
    const float c1B0 = __fadd_rn(__fmaf_rn(xv.w, w1_01, __fmul_rn(xv.z, w1_00)), b1_0);
    const float c1B1 = __fadd_rn(__fmaf_rn(xv.w, w1_11, __fmul_rn(xv.z, w1_10)), b1_1);

    float m1A0 = 0.f, m1A1 = 0.f, m1B0 = 0.f, m1B1 = 0.f;
    float m2A0 = 0.f, m2A1 = 0.f, m2B0 = 0.f, m2B1 = 0.f;
    // initial "previous spike" = Heaviside(0 - th) (reference reset at t=0)
    const float s10 = (0.f > th1) ? 1.f : 0.f;
    const float s20 = (0.f > th2) ? 1.f : 0.f;
    float s1A0 = s10, s1A1 = s10, s1B0 = s10, s1B1 = s10;
    float s2A0 = s20, s2A1 = s20, s2B0 = s20, s2B1 = s20;

    if (c) {
#pragma unroll
        for (int tt = 0; tt < 16; tt++) { SNN_STEP2(); }
    }

    const int TBp = 32 * Bp;            // float4 rows per output array
    float4* __restrict__ o_spk1 = out;
    float4* __restrict__ o_spk2 = out + TBp;
    float4* __restrict__ o_mem2 = out + 2 * (size_t)TBp;

    int idx = (c * 16) * Bp + p;
#pragma unroll
    for (int tt = 0; tt < 16; tt++) {
        SNN_STEP2();
        __stcs(&o_spk1[idx], make_float4(s1A0, s1A1, s1B0, s1B1));
        __stcs(&o_spk2[idx], make_float4(s2A0, s2A1, s2B0, s2B1));
        __stcs(&o_mem2[idx], make_float4(m2A0, m2A1, m2B0, m2B1));
        idx += Bp;
    }
}

// Generic fallback: one element per thread, any T / odd B (== R3 structure).
__global__ __launch_bounds__(256)
void snn_generic(const float2* __restrict__ x,
                 const float* __restrict__ fc1_w, const float* __restrict__ fc1_b,
                 const float* __restrict__ beta1, const float* __restrict__ thr1,
                 const float* __restrict__ fc2_w, const float* __restrict__ fc2_b,
                 const float* __restrict__ beta2, const float* __restrict__ thr2,
                 float2* __restrict__ out, int B, int T)
{
    const int b = blockIdx.x * blockDim.x + threadIdx.x;
    if (b >= B) return;

    SNN_LOAD_PARAMS();

    const float2 xv = __ldg(&x[b]);
    const float cur1_0 = __fadd_rn(__fmaf_rn(xv.y, w1_01, __fmul_rn(xv.x, w1_00)), b1_0);
    const float cur1_1 = __fadd_rn(__fmaf_rn(xv.y, w1_11, __fmul_rn(xv.x, w1_10)), b1_1);

    float mem1_0 = 0.f, mem1_1 = 0.f, mem2_0 = 0.f, mem2_1 = 0.f;
    float s1_0 = (0.f > th1) ? 1.f : 0.f, s1_1 = s1_0;
    float s2_0 = (0.f > th2) ? 1.f : 0.f, s2_1 = s2_0;

    const size_t TB = (size_t)T * (size_t)B;
    float2* __restrict__ o_spk1 = out;
    float2* __restrict__ o_spk2 = out + TB;
    float2* __restrict__ o_mem2 = out + 2 * TB;

    for (int t = 0; t < T; t++) {
        const float r1_0 = s1_0 != 0.f ? th1 : 0.f;
        const float r1_1 = s1_1 != 0.f ? th1 : 0.f;
        mem1_0 = __fsub_rn(__fadd_rn(__fmul_rn(bt1, mem1_0), cur1_0), r1_0);
        mem1_1 = __fsub_rn(__fadd_rn(__fmul_rn(bt1, mem1_1), cur1_1), r1_1);
        s1_0 = (mem1_0 > th1) ? 1.f : 0.f;
        s1_1 = (mem1_1 > th1) ? 1.f : 0.f;
        const float cur2_0 = __fadd_rn(__fmaf_rn(s1_1, w2_01, __fmul_rn(s1_0, w2_00)), b2_0);
        const float cur2_1 = __fadd_rn(__fmaf_rn(s1_1, w2_11, __fmul_rn(s1_0, w2_10)), b2_1);
        const float r2_0 = s2_0 != 0.f ? th2 : 0.f;
        const float r2_1 = s2_1 != 0.f ? th2 : 0.f;
        mem2_0 = __fsub_rn(__fadd_rn(__fmul_rn(bt2, mem2_0), cur2_0), r2_0);
        mem2_1 = __fsub_rn(__fadd_rn(__fmul_rn(bt2, mem2_1), cur2_1), r2_1);
        s2_0 = (mem2_0 > th2) ? 1.f : 0.f;
        s2_1 = (mem2_1 > th2) ? 1.f : 0.f;

        const size_t idx = (size_t)t * (size_t)B + (size_t)b;
        __stcs(&o_spk1[idx], make_float2(s1_0, s1_1));
        __stcs(&o_spk2[idx], make_float2(s2_0, s2_1));
        __stcs(&o_mem2[idx], make_float2(mem2_0, mem2_1));
    }
}

extern "C" void kernel_launch(void* const* d_in, const int* in_sizes, int n_in,
                              void* d_out, int out_size) {
    const float*  fc1_w = (const float*)d_in[1];
    const float*  fc1_b = (const float*)d_in[2];
    const float*  beta1 = (const float*)d_in[3];
    const float*  thr1  = (const float*)d_in[4];
    const float*  fc2_w = (const float*)d_in[5];
    const float*  fc2_b = (const float*)d_in[6];
    const float*  beta2 = (const float*)d_in[7];
    const float*  thr2  = (const float*)d_in[8];

    const int B = in_sizes[0] / 2;          // x is [B, 2]
    const int T = out_size / (6 * B);       // out = 3 arrays of [T, B, 2]

    const int threads = 256;

    if (T == 32 && (B & 1) == 0) {
        const int Bp = B / 2;
        const long long items = 2LL * Bp;   // (pair, 16-step half)
        const int blocks = (int)((items + threads - 1) / threads);
        snn_pair_half32<<<blocks, threads>>>((const float4*)d_in[0],
            fc1_w, fc1_b, beta1, thr1, fc2_w, fc2_b, beta2, thr2,
            (float4*)d_out, Bp);
    } else {
        const int blocks = (B + threads - 1) / threads;
        snn_generic<<<blocks, threads>>>((const float2*)d_in[0],
            fc1_w, fc1_b, beta1, thr1, fc2_w, fc2_b, beta2, thr2,
            (float2*)d_out, B, T);
    }
}